// round 2
// baseline (speedup 1.0000x reference)
#include <cuda_runtime.h>

#define NN 50000
#define NE 600000
#define HID 128
#define NG 128
#define NC 10
#define NL 4

// ---------------- scratch (static device globals; no allocation) ----------------
// NOTE: edge_index / batch are int32 (JAX x64 disabled downcasts int64 -> int32).
__device__ __align__(16) float g_h[NN * HID];
__device__ __align__(16) float g_agg[NN * HID];
__device__ __align__(16) float g_y1[NN * HID];
__device__ __align__(16) float g_y2[NN * HID];
__device__ float g_colsum[HID];
__device__ float g_colsq[HID];
__device__ __align__(16) float g_sc1[HID], g_sh1[HID], g_sc2[HID], g_sh2[HID];
__device__ __align__(16) float g_pooled[(NL + 1) * NG * HID];
__device__ float g_counts[NG];

// ---------------- GEMM: C[n,128] = f(A)[n,128] @ W[128,128] + bias ----------------
// MODE 0: a = A                     (embedding)
// MODE 1: a = (1+eps)*A + A2        (GIN combine: h + agg)
// MODE 2: a = relu(A*bnsc + bnsh)   (BN+ReLU applied on read of y1)
// STATS: accumulate per-column sum / sumsq of the OUTPUT into g_colsum/g_colsq.
template <int MODE, bool STATS>
__global__ void __launch_bounds__(256) gemm_k(
    const float* __restrict__ A, const float* __restrict__ A2,
    const float* __restrict__ epsPtr, int layer,
    const float* __restrict__ bnsc, const float* __restrict__ bnsh,
    const float* __restrict__ W, const float* __restrict__ bias,
    float* __restrict__ out, int n)
{
    __shared__ float As[16][132];   // [k][row], padded
    __shared__ float Bs[16][128];   // [k][col]
    __shared__ float s_sum[128];
    __shared__ float s_sq[128];

    const int tid = threadIdx.x;
    const int tx = tid & 15;        // col group
    const int ty = tid >> 4;        // row group
    const int row0 = blockIdx.x * 128;

    float onePlusEps = 1.0f;
    if (MODE == 1) onePlusEps = 1.0f + epsPtr[layer];

    if (STATS && tid < 128) { s_sum[tid] = 0.0f; s_sq[tid] = 0.0f; }

    float acc[8][8];
#pragma unroll
    for (int i = 0; i < 8; i++)
#pragma unroll
        for (int j = 0; j < 8; j++) acc[i][j] = 0.0f;

    for (int k0 = 0; k0 < 128; k0 += 16) {
        // load A tile (128 rows x 16 k), with input transform
        {
            const int kk = tid & 15;
            const int rb = tid >> 4;
#pragma unroll
            for (int p = 0; p < 8; p++) {
                const int r = rb + p * 16;
                const int row = row0 + r;
                float a = 0.0f;
                if (row < n) {
                    const int idx = row * 128 + k0 + kk;
                    if (MODE == 0) {
                        a = A[idx];
                    } else if (MODE == 1) {
                        a = fmaf(onePlusEps, A[idx], A2[idx]);
                    } else {
                        a = fmaxf(fmaf(A[idx], bnsc[k0 + kk], bnsh[k0 + kk]), 0.0f);
                    }
                }
                As[kk][r] = a;
            }
        }
        // load B tile (16 k x 128 cols)
        {
            const int c = tid & 127;
            const int kb = tid >> 7;
#pragma unroll
            for (int p = 0; p < 8; p++) {
                const int k = kb + p * 2;
                Bs[k][c] = W[(k0 + k) * 128 + c];
            }
        }
        __syncthreads();
#pragma unroll
        for (int k = 0; k < 16; k++) {
            float a[8], b[8];
#pragma unroll
            for (int i = 0; i < 8; i++) a[i] = As[k][ty + 16 * i];
#pragma unroll
            for (int j = 0; j < 8; j++) b[j] = Bs[k][tx + 16 * j];
#pragma unroll
            for (int i = 0; i < 8; i++)
#pragma unroll
                for (int j = 0; j < 8; j++)
                    acc[i][j] = fmaf(a[i], b[j], acc[i][j]);
        }
        __syncthreads();
    }

    // epilogue: bias add, store, column stats
#pragma unroll
    for (int j = 0; j < 8; j++) {
        const int c = tx + 16 * j;
        const float bv = bias[c];
        float psum = 0.0f, psq = 0.0f;
#pragma unroll
        for (int i = 0; i < 8; i++) {
            const int row = row0 + ty + 16 * i;
            if (row < n) {
                const float v = acc[i][j] + bv;
                out[row * 128 + c] = v;
                psum += v;
                psq = fmaf(v, v, psq);
            }
        }
        if (STATS) {
            atomicAdd(&s_sum[c], psum);
            atomicAdd(&s_sq[c], psq);
        }
    }
    if (STATS) {
        __syncthreads();
        if (tid < 128) {
            atomicAdd(&g_colsum[tid], s_sum[tid]);
            atomicAdd(&g_colsq[tid], s_sq[tid]);
        }
    }
}

// ---------------- finalize BN: scale/shift per column, reset stats ----------------
__global__ void bnfin_k(const float* __restrict__ gam, const float* __restrict__ bet,
                        float* __restrict__ sc, float* __restrict__ sh)
{
    const int c = threadIdx.x;
    const float inv_n = 1.0f / (float)NN;
    const float m = g_colsum[c] * inv_n;
    const float var = g_colsq[c] * inv_n - m * m;
    const float s = gam[c] * rsqrtf(var + 1e-5f);
    sc[c] = s;
    sh[c] = bet[c] - m * s;
    g_colsum[c] = 0.0f;
    g_colsq[c] = 0.0f;
}

// ---------------- edge scatter: agg[dst] += h[src]  (warp per edge, float4 RED) ----------------
__global__ void __launch_bounds__(256) scatter_k(const int* __restrict__ src,
                                                 const int* __restrict__ dst)
{
    const int e = blockIdx.x * 8 + (threadIdx.x >> 5);
    if (e >= NE) return;
    const int lane = threadIdx.x & 31;
    const int s = src[e];
    const int d = dst[e];
    const float4 v = *reinterpret_cast<const float4*>(&g_h[s * 128 + lane * 4]);
    atomicAdd(reinterpret_cast<float4*>(&g_agg[d * 128 + lane * 4]), v);
}

// ---------------- residual update + graph pooling (warp per node) ----------------
// UPDATE: h += relu(y2*sc+sh), then pooled[batch] += h.  !UPDATE: pooled[batch] += h only.
template <bool UPDATE>
__global__ void __launch_bounds__(256) pool_k(const float* __restrict__ y2,
                                              const float* __restrict__ sc,
                                              const float* __restrict__ sh,
                                              const int* __restrict__ batch,
                                              float* __restrict__ pooled)
{
    const int node = blockIdx.x * 8 + (threadIdx.x >> 5);
    if (node >= NN) return;
    const int lane = threadIdx.x & 31;
    const int g = batch[node];
    float4 hv = *reinterpret_cast<const float4*>(&g_h[node * 128 + lane * 4]);
    if (UPDATE) {
        const float4 yv = *reinterpret_cast<const float4*>(&y2[node * 128 + lane * 4]);
        const float4 scv = *reinterpret_cast<const float4*>(&sc[lane * 4]);
        const float4 shv = *reinterpret_cast<const float4*>(&sh[lane * 4]);
        hv.x += fmaxf(fmaf(yv.x, scv.x, shv.x), 0.0f);
        hv.y += fmaxf(fmaf(yv.y, scv.y, shv.y), 0.0f);
        hv.z += fmaxf(fmaf(yv.z, scv.z, shv.z), 0.0f);
        hv.w += fmaxf(fmaf(yv.w, scv.w, shv.w), 0.0f);
        *reinterpret_cast<float4*>(&g_h[node * 128 + lane * 4]) = hv;
    }
    atomicAdd(reinterpret_cast<float4*>(&pooled[g * 128 + lane * 4]), hv);
}

// ---------------- per-graph node counts ----------------
__global__ void counts_k(const int* __restrict__ batch)
{
    const int i = blockIdx.x * 256 + threadIdx.x;
    if (i < NN) atomicAdd(&g_counts[batch[i]], 1.0f);
}

// ---------------- prediction heads: score[g,c] = sum_l pooled_l[g]/cnt @ pw_l + pb_l ----------------
__global__ void head_k(const float* __restrict__ pw, const float* __restrict__ pb,
                       float* __restrict__ out)
{
    const int g = blockIdx.x;
    const int c = threadIdx.x;
    if (c >= NC) return;
    const float inv_cnt = 1.0f / fmaxf(g_counts[g], 1.0f);
    float acc = 0.0f;
#pragma unroll
    for (int l = 0; l <= NL; l++) {
        const float* p = &g_pooled[(l * NG + g) * HID];
        float a = 0.0f;
#pragma unroll 8
        for (int f = 0; f < HID; f++)
            a = fmaf(p[f], pw[(l * HID + f) * NC + c], a);
        acc += a * inv_cnt + pb[l * NC + c];
    }
    out[g * NC + c] = acc;
}

// ---------------- launch ----------------
extern "C" void kernel_launch(void* const* d_in, const int* in_sizes, int n_in,
                              void* d_out, int out_size)
{
    const float* x     = (const float*)d_in[0];
    const int*   ei    = (const int*)d_in[1];     // [2, NE] int32
    const int*   batch = (const int*)d_in[2];     // [NN] int32
    const float* emb_w = (const float*)d_in[3];
    const float* emb_b = (const float*)d_in[4];
    const float* eps   = (const float*)d_in[5];
    const float* w1    = (const float*)d_in[6];
    const float* b1    = (const float*)d_in[7];
    const float* bn1g  = (const float*)d_in[8];
    const float* bn1b  = (const float*)d_in[9];
    const float* w2    = (const float*)d_in[10];
    const float* b2    = (const float*)d_in[11];
    const float* bng   = (const float*)d_in[12];
    const float* bnb   = (const float*)d_in[13];
    const float* pw    = (const float*)d_in[14];
    const float* pb    = (const float*)d_in[15];
    float*       out   = (float*)d_out;

    void *p_h, *p_agg, *p_y1, *p_y2, *p_pooled, *p_counts, *p_colsum, *p_colsq;
    void *p_sc1, *p_sh1, *p_sc2, *p_sh2;
    cudaGetSymbolAddress(&p_h,      g_h);
    cudaGetSymbolAddress(&p_agg,    g_agg);
    cudaGetSymbolAddress(&p_y1,     g_y1);
    cudaGetSymbolAddress(&p_y2,     g_y2);
    cudaGetSymbolAddress(&p_pooled, g_pooled);
    cudaGetSymbolAddress(&p_counts, g_counts);
    cudaGetSymbolAddress(&p_colsum, g_colsum);
    cudaGetSymbolAddress(&p_colsq,  g_colsq);
    cudaGetSymbolAddress(&p_sc1,    g_sc1);
    cudaGetSymbolAddress(&p_sh1,    g_sh1);
    cudaGetSymbolAddress(&p_sc2,    g_sc2);
    cudaGetSymbolAddress(&p_sh2,    g_sh2);

    cudaMemsetAsync(p_pooled, 0, sizeof(float) * (NL + 1) * NG * HID);
    cudaMemsetAsync(p_counts, 0, sizeof(float) * NG);
    cudaMemsetAsync(p_colsum, 0, sizeof(float) * HID);
    cudaMemsetAsync(p_colsq,  0, sizeof(float) * HID);

    counts_k<<<(NN + 255) / 256, 256>>>(batch);

    const int GB = (NN + 127) / 128;

    // embedding: h = x @ emb_w + emb_b
    gemm_k<0, false><<<GB, 256>>>(x, nullptr, nullptr, 0, nullptr, nullptr,
                                  emb_w, emb_b, (float*)p_h, NN);
    // pool hidden[0]
    pool_k<false><<<(NN + 7) / 8, 256>>>(nullptr, nullptr, nullptr, batch, (float*)p_pooled);

    for (int l = 0; l < NL; l++) {
        cudaMemsetAsync(p_agg, 0, sizeof(float) * NN * HID);
        scatter_k<<<(NE + 7) / 8, 256>>>(ei, ei + NE);

        // y1 = ((1+eps)h + agg) @ w1 + b1  (+ column stats)
        gemm_k<1, true><<<GB, 256>>>((const float*)p_h, (const float*)p_agg, eps, l,
                                     nullptr, nullptr,
                                     w1 + (size_t)l * HID * HID, b1 + l * HID,
                                     (float*)p_y1, NN);
        bnfin_k<<<1, 128>>>(bn1g + l * HID, bn1b + l * HID, (float*)p_sc1, (float*)p_sh1);

        // y2 = relu(bn1(y1)) @ w2 + b2  (+ column stats)
        gemm_k<2, true><<<GB, 256>>>((const float*)p_y1, nullptr, nullptr, 0,
                                     (const float*)p_sc1, (const float*)p_sh1,
                                     w2 + (size_t)l * HID * HID, b2 + l * HID,
                                     (float*)p_y2, NN);
        bnfin_k<<<1, 128>>>(bng + l * HID, bnb + l * HID, (float*)p_sc2, (float*)p_sh2);

        // h += relu(bn2(y2)); pool hidden[l+1]
        pool_k<true><<<(NN + 7) / 8, 256>>>((const float*)p_y2, (const float*)p_sc2,
                                            (const float*)p_sh2, batch,
                                            (float*)p_pooled + (size_t)(l + 1) * NG * HID);
    }

    head_k<<<NG, 32>>>(pw, pb, out);
}

// round 4
// speedup vs baseline: 1.1627x; 1.1627x over previous
#include <cuda_runtime.h>
#include <cuda_bf16.h>
#include <cstdint>

#define NN 50000
#define NE 600000
#define HID 128
#define NG 128
#define NC 10
#define NL 4

// ---------------- scratch ----------------
__device__ __align__(16) float g_h[NN * HID];
__device__ __align__(16) float g_agg[NN * HID];
__device__ __align__(16) float g_y1[NN * HID];
__device__ __align__(16) float g_y2[NN * HID];
__device__ float g_colsum[HID];
__device__ float g_colsq[HID];
__device__ __align__(16) float g_sc1[HID], g_sh1[HID], g_sc2[HID], g_sh2[HID];
__device__ __align__(16) float g_pooled[(NL + 1) * NG * HID];
__device__ float g_counts[NG];

// ---------------- helpers ----------------
__device__ __forceinline__ uint32_t smem_u32(const void* p) {
    uint32_t a;
    asm("{ .reg .u64 t; cvta.to.shared.u64 t, %1; cvt.u32.u64 %0, t; }" : "=r"(a) : "l"(p));
    return a;
}

__device__ __forceinline__ void ldsm4(uint32_t* r, uint32_t addr) {
    asm volatile("ldmatrix.sync.aligned.m8n8.x4.shared.b16 {%0,%1,%2,%3}, [%4];"
                 : "=r"(r[0]), "=r"(r[1]), "=r"(r[2]), "=r"(r[3]) : "r"(addr));
}
__device__ __forceinline__ void ldsm2(uint32_t* r, uint32_t addr) {
    asm volatile("ldmatrix.sync.aligned.m8n8.x2.shared.b16 {%0,%1}, [%2];"
                 : "=r"(r[0]), "=r"(r[1]) : "r"(addr));
}
__device__ __forceinline__ void mma16816(float* c, const uint32_t* a, const uint32_t* b) {
    asm volatile(
        "mma.sync.aligned.m16n8k16.row.col.f32.bf16.bf16.f32 "
        "{%0,%1,%2,%3}, {%4,%5,%6,%7}, {%8,%9}, {%0,%1,%2,%3};"
        : "+f"(c[0]), "+f"(c[1]), "+f"(c[2]), "+f"(c[3])
        : "r"(a[0]), "r"(a[1]), "r"(a[2]), "r"(a[3]), "r"(b[0]), "r"(b[1]));
}

// tile leading dim in bf16 elems: 128 + 8 pad -> 272B rows, conflict-free LDSM
#define LDT 136
#define TILE_BYTES (128 * LDT * 2)
#define SM_TOT (4 * TILE_BYTES)

// ---------------- tensor GEMM: out[n,128] = f(A)[n,128] @ W[128,128] + bias ----------------
// MODE 0: a = A ; MODE 1: a = (1+eps)*A + A2 ; MODE 2: a = relu(A*bnsc + bnsh)
template <int MODE>
__global__ void __launch_bounds__(256) tgemm_k(
    const float* __restrict__ A, const float* __restrict__ A2,
    const float* __restrict__ epsPtr, int layer,
    const float* __restrict__ bnsc, const float* __restrict__ bnsh,
    const float* __restrict__ W, const float* __restrict__ bias,
    float* __restrict__ out, int n)
{
    extern __shared__ char smem[];
    __nv_bfloat16* Ahi = (__nv_bfloat16*)(smem);
    __nv_bfloat16* Alo = (__nv_bfloat16*)(smem + TILE_BYTES);
    __nv_bfloat16* Bhi = (__nv_bfloat16*)(smem + 2 * TILE_BYTES);
    __nv_bfloat16* Blo = (__nv_bfloat16*)(smem + 3 * TILE_BYTES);

    const int tid = threadIdx.x;
    const int lane = tid & 31;
    const int wid = tid >> 5;
    const int wm = wid & 3;       // 4 warps along M (32 rows each)
    const int wn = wid >> 2;      // 2 warps along N (64 cols each)
    const int row0 = blockIdx.x * 128;

    // ---- load A tile: thread owns row tid/2, cols (tid&1)*64 .. +64 ----
    {
        const int r = tid >> 1;
        const int row = row0 + r;
        const int cb = (tid & 1) * 64;
        float oe = 1.0f;
        if (MODE == 1) oe = 1.0f + epsPtr[layer];
        const float4* Ar  = (const float4*)(A + (size_t)row * 128 + cb);
        const float4* A2r = (MODE == 1) ? (const float4*)(A2 + (size_t)row * 128 + cb) : nullptr;
#pragma unroll 4
        for (int i = 0; i < 16; i++) {
            float v[4] = {0.f, 0.f, 0.f, 0.f};
            if (row < n) {
                float4 a = Ar[i];
                if (MODE == 1) {
                    float4 b = A2r[i];
                    v[0] = fmaf(oe, a.x, b.x); v[1] = fmaf(oe, a.y, b.y);
                    v[2] = fmaf(oe, a.z, b.z); v[3] = fmaf(oe, a.w, b.w);
                } else if (MODE == 2) {
                    const float4 sc = ((const float4*)(bnsc + cb))[i];
                    const float4 sh = ((const float4*)(bnsh + cb))[i];
                    v[0] = fmaxf(fmaf(a.x, sc.x, sh.x), 0.f);
                    v[1] = fmaxf(fmaf(a.y, sc.y, sh.y), 0.f);
                    v[2] = fmaxf(fmaf(a.z, sc.z, sh.z), 0.f);
                    v[3] = fmaxf(fmaf(a.w, sc.w, sh.w), 0.f);
                } else {
                    v[0] = a.x; v[1] = a.y; v[2] = a.z; v[3] = a.w;
                }
            }
            const int base = r * LDT + cb + i * 4;
#pragma unroll
            for (int u = 0; u < 4; u++) {
                __nv_bfloat16 h = __float2bfloat16(v[u]);
                Ahi[base + u] = h;
                Alo[base + u] = __float2bfloat16(v[u] - __bfloat162float(h));
            }
        }
    }
    // ---- load B tile transposed: B[nn][k] = W[k][nn] ----
    {
        const int nn = tid & 127;
        const int k0 = (tid >> 7) * 64;
#pragma unroll 8
        for (int k = k0; k < k0 + 64; k++) {
            const float w = W[(size_t)k * 128 + nn];
            __nv_bfloat16 h = __float2bfloat16(w);
            Bhi[nn * LDT + k] = h;
            Blo[nn * LDT + k] = __float2bfloat16(w - __bfloat162float(h));
        }
    }
    __syncthreads();

    // ---- warp mma mainloop: 32x64 per warp, K=128 in 8 steps ----
    float acc[2][8][4];
#pragma unroll
    for (int mt = 0; mt < 2; mt++)
#pragma unroll
        for (int j = 0; j < 8; j++)
#pragma unroll
            for (int u = 0; u < 4; u++) acc[mt][j][u] = 0.f;

    const uint32_t sAhi = smem_u32(Ahi), sAlo = smem_u32(Alo);
    const uint32_t sBhi = smem_u32(Bhi), sBlo = smem_u32(Blo);

    // A ldmatrix lane addressing: row = wm*32 + mt*16 + (lane%16); col = ks*16 + (lane/16)*8
    const int aRow = wm * 32 + (lane & 15);
    const int aCol = (lane >> 4) * 8;
    // B ldmatrix (x2, lanes 0-15): row = wn*64 + j*8 + (lane%8); col = ks*16 + ((lane/8)&1)*8
    const int bRow = wn * 64 + (lane & 7);
    const int bCol = ((lane >> 3) & 1) * 8;

#pragma unroll
    for (int ks = 0; ks < 8; ks++) {
        uint32_t ahi[2][4], alo[2][4], bhi[8][2], blo[8][2];
        const int kc = ks * 16;
#pragma unroll
        for (int mt = 0; mt < 2; mt++) {
            const uint32_t off = ((aRow + mt * 16) * LDT + kc + aCol) * 2;
            ldsm4(ahi[mt], sAhi + off);
            ldsm4(alo[mt], sAlo + off);
        }
#pragma unroll
        for (int j = 0; j < 8; j++) {
            const uint32_t off = ((bRow + j * 8) * LDT + kc + bCol) * 2;
            ldsm2(bhi[j], sBhi + off);
            ldsm2(blo[j], sBlo + off);
        }
#pragma unroll
        for (int mt = 0; mt < 2; mt++)
#pragma unroll
            for (int j = 0; j < 8; j++) {
                mma16816(acc[mt][j], ahi[mt], bhi[j]);
                mma16816(acc[mt][j], ahi[mt], blo[j]);
                mma16816(acc[mt][j], alo[mt], bhi[j]);
            }
    }

    // ---- epilogue: bias + store ----
#pragma unroll
    for (int mt = 0; mt < 2; mt++) {
        const int r_lo = row0 + wm * 32 + mt * 16 + (lane >> 2);
        const int r_hi = r_lo + 8;
#pragma unroll
        for (int j = 0; j < 8; j++) {
            const int c = wn * 64 + j * 8 + (lane & 3) * 2;
            const float b0 = bias[c], b1 = bias[c + 1];
            if (r_lo < n) {
                float2 v = {acc[mt][j][0] + b0, acc[mt][j][1] + b1};
                *(float2*)(out + (size_t)r_lo * 128 + c) = v;
            }
            if (r_hi < n) {
                float2 v = {acc[mt][j][2] + b0, acc[mt][j][3] + b1};
                *(float2*)(out + (size_t)r_hi * 128 + c) = v;
            }
        }
    }
}

// ---------------- BN column stats ----------------
__global__ void __launch_bounds__(256) stats_k(const float* __restrict__ y)
{
    __shared__ float ss[128], sq[128];
    const int tid = threadIdx.x;
    if (tid < 128) { ss[tid] = 0.f; sq[tid] = 0.f; }
    __syncthreads();
    const int c4 = tid & 31;
    float4 s = {0.f, 0.f, 0.f, 0.f}, q = {0.f, 0.f, 0.f, 0.f};
    for (int r = blockIdx.x * 8 + (tid >> 5); r < NN; r += gridDim.x * 8) {
        const float4 v = *(const float4*)(y + (size_t)r * 128 + c4 * 4);
        s.x += v.x; s.y += v.y; s.z += v.z; s.w += v.w;
        q.x = fmaf(v.x, v.x, q.x); q.y = fmaf(v.y, v.y, q.y);
        q.z = fmaf(v.z, v.z, q.z); q.w = fmaf(v.w, v.w, q.w);
    }
    atomicAdd(&ss[c4 * 4 + 0], s.x); atomicAdd(&ss[c4 * 4 + 1], s.y);
    atomicAdd(&ss[c4 * 4 + 2], s.z); atomicAdd(&ss[c4 * 4 + 3], s.w);
    atomicAdd(&sq[c4 * 4 + 0], q.x); atomicAdd(&sq[c4 * 4 + 1], q.y);
    atomicAdd(&sq[c4 * 4 + 2], q.z); atomicAdd(&sq[c4 * 4 + 3], q.w);
    __syncthreads();
    if (tid < 128) {
        atomicAdd(&g_colsum[tid], ss[tid]);
        atomicAdd(&g_colsq[tid], sq[tid]);
    }
}

// ---------------- finalize BN ----------------
__global__ void bnfin_k(const float* __restrict__ gam, const float* __restrict__ bet,
                        float* __restrict__ sc, float* __restrict__ sh)
{
    const int c = threadIdx.x;
    const float inv_n = 1.0f / (float)NN;
    const float m = g_colsum[c] * inv_n;
    const float var = g_colsq[c] * inv_n - m * m;
    const float s = gam[c] * rsqrtf(var + 1e-5f);
    sc[c] = s;
    sh[c] = bet[c] - m * s;
    g_colsum[c] = 0.0f;
    g_colsq[c] = 0.0f;
}

// ---------------- edge scatter ----------------
__global__ void __launch_bounds__(256) scatter_k(const int* __restrict__ src,
                                                 const int* __restrict__ dst)
{
    const int e = blockIdx.x * 8 + (threadIdx.x >> 5);
    if (e >= NE) return;
    const int lane = threadIdx.x & 31;
    const int s = src[e];
    const int d = dst[e];
    const float4 v = *reinterpret_cast<const float4*>(&g_h[s * 128 + lane * 4]);
    atomicAdd(reinterpret_cast<float4*>(&g_agg[d * 128 + lane * 4]), v);
}

// ---------------- residual update + pooling ----------------
template <bool UPDATE>
__global__ void __launch_bounds__(256) pool_k(const float* __restrict__ y2,
                                              const float* __restrict__ sc,
                                              const float* __restrict__ sh,
                                              const int* __restrict__ batch,
                                              float* __restrict__ pooled)
{
    const int node = blockIdx.x * 8 + (threadIdx.x >> 5);
    if (node >= NN) return;
    const int lane = threadIdx.x & 31;
    const int g = batch[node];
    float4 hv = *reinterpret_cast<const float4*>(&g_h[node * 128 + lane * 4]);
    if (UPDATE) {
        const float4 yv = *reinterpret_cast<const float4*>(&y2[node * 128 + lane * 4]);
        const float4 scv = *reinterpret_cast<const float4*>(&sc[lane * 4]);
        const float4 shv = *reinterpret_cast<const float4*>(&sh[lane * 4]);
        hv.x += fmaxf(fmaf(yv.x, scv.x, shv.x), 0.0f);
        hv.y += fmaxf(fmaf(yv.y, scv.y, shv.y), 0.0f);
        hv.z += fmaxf(fmaf(yv.z, scv.z, shv.z), 0.0f);
        hv.w += fmaxf(fmaf(yv.w, scv.w, shv.w), 0.0f);
        *reinterpret_cast<float4*>(&g_h[node * 128 + lane * 4]) = hv;
    }
    atomicAdd(reinterpret_cast<float4*>(&pooled[g * 128 + lane * 4]), hv);
}

// ---------------- counts ----------------
__global__ void counts_k(const int* __restrict__ batch)
{
    const int i = blockIdx.x * 256 + threadIdx.x;
    if (i < NN) atomicAdd(&g_counts[batch[i]], 1.0f);
}

// ---------------- heads ----------------
__global__ void head_k(const float* __restrict__ pw, const float* __restrict__ pb,
                       float* __restrict__ out)
{
    const int g = blockIdx.x;
    const int c = threadIdx.x;
    if (c >= NC) return;
    const float inv_cnt = 1.0f / fmaxf(g_counts[g], 1.0f);
    float acc = 0.0f;
#pragma unroll
    for (int l = 0; l <= NL; l++) {
        const float* p = &g_pooled[(l * NG + g) * HID];
        float a = 0.0f;
#pragma unroll 8
        for (int f = 0; f < HID; f++)
            a = fmaf(p[f], pw[(l * HID + f) * NC + c], a);
        acc += a * inv_cnt + pb[l * NC + c];
    }
    out[g * NC + c] = acc;
}

// ---------------- launch ----------------
extern "C" void kernel_launch(void* const* d_in, const int* in_sizes, int n_in,
                              void* d_out, int out_size)
{
    const float* x     = (const float*)d_in[0];
    const int*   ei    = (const int*)d_in[1];
    const int*   batch = (const int*)d_in[2];
    const float* emb_w = (const float*)d_in[3];
    const float* emb_b = (const float*)d_in[4];
    const float* eps   = (const float*)d_in[5];
    const float* w1    = (const float*)d_in[6];
    const float* b1    = (const float*)d_in[7];
    const float* bn1g  = (const float*)d_in[8];
    const float* bn1b  = (const float*)d_in[9];
    const float* w2    = (const float*)d_in[10];
    const float* b2    = (const float*)d_in[11];
    const float* bng   = (const float*)d_in[12];
    const float* bnb   = (const float*)d_in[13];
    const float* pw    = (const float*)d_in[14];
    const float* pb    = (const float*)d_in[15];
    float*       out   = (float*)d_out;

    void *p_h, *p_agg, *p_y1, *p_y2, *p_pooled, *p_counts, *p_colsum, *p_colsq;
    void *p_sc1, *p_sh1, *p_sc2, *p_sh2;
    cudaGetSymbolAddress(&p_h,      g_h);
    cudaGetSymbolAddress(&p_agg,    g_agg);
    cudaGetSymbolAddress(&p_y1,     g_y1);
    cudaGetSymbolAddress(&p_y2,     g_y2);
    cudaGetSymbolAddress(&p_pooled, g_pooled);
    cudaGetSymbolAddress(&p_counts, g_counts);
    cudaGetSymbolAddress(&p_colsum, g_colsum);
    cudaGetSymbolAddress(&p_colsq,  g_colsq);
    cudaGetSymbolAddress(&p_sc1,    g_sc1);
    cudaGetSymbolAddress(&p_sh1,    g_sh1);
    cudaGetSymbolAddress(&p_sc2,    g_sc2);
    cudaGetSymbolAddress(&p_sh2,    g_sh2);

    cudaFuncSetAttribute(tgemm_k<0>, cudaFuncAttributeMaxDynamicSharedMemorySize, SM_TOT);
    cudaFuncSetAttribute(tgemm_k<1>, cudaFuncAttributeMaxDynamicSharedMemorySize, SM_TOT);
    cudaFuncSetAttribute(tgemm_k<2>, cudaFuncAttributeMaxDynamicSharedMemorySize, SM_TOT);

    cudaMemsetAsync(p_pooled, 0, sizeof(float) * (NL + 1) * NG * HID);
    cudaMemsetAsync(p_counts, 0, sizeof(float) * NG);
    cudaMemsetAsync(p_colsum, 0, sizeof(float) * HID);
    cudaMemsetAsync(p_colsq,  0, sizeof(float) * HID);

    counts_k<<<(NN + 255) / 256, 256>>>(batch);

    const int GB = (NN + 127) / 128;

    // embedding
    tgemm_k<0><<<GB, 256, SM_TOT>>>(x, nullptr, nullptr, 0, nullptr, nullptr,
                                    emb_w, emb_b, (float*)p_h, NN);
    pool_k<false><<<(NN + 7) / 8, 256>>>(nullptr, nullptr, nullptr, batch, (float*)p_pooled);

    for (int l = 0; l < NL; l++) {
        cudaMemsetAsync(p_agg, 0, sizeof(float) * NN * HID);
        scatter_k<<<(NE + 7) / 8, 256>>>(ei, ei + NE);

        tgemm_k<1><<<GB, 256, SM_TOT>>>((const float*)p_h, (const float*)p_agg, eps, l,
                                        nullptr, nullptr,
                                        w1 + (size_t)l * HID * HID, b1 + l * HID,
                                        (float*)p_y1, NN);
        stats_k<<<256, 256>>>((const float*)p_y1);
        bnfin_k<<<1, 128>>>(bn1g + l * HID, bn1b + l * HID, (float*)p_sc1, (float*)p_sh1);

        tgemm_k<2><<<GB, 256, SM_TOT>>>((const float*)p_y1, nullptr, nullptr, 0,
                                        (const float*)p_sc1, (const float*)p_sh1,
                                        w2 + (size_t)l * HID * HID, b2 + l * HID,
                                        (float*)p_y2, NN);
        stats_k<<<256, 256>>>((const float*)p_y2);
        bnfin_k<<<1, 128>>>(bng + l * HID, bnb + l * HID, (float*)p_sc2, (float*)p_sh2);

        pool_k<true><<<(NN + 7) / 8, 256>>>((const float*)p_y2, (const float*)p_sc2,
                                            (const float*)p_sh2, batch,
                                            (float*)p_pooled + (size_t)(l + 1) * NG * HID);
    }

    head_k<<<NG, 32>>>(pw, pb, out);
}

// round 5
// speedup vs baseline: 1.3492x; 1.1604x over previous
#include <cuda_runtime.h>
#include <cuda_bf16.h>
#include <cstdint>

#define NN 50000
#define NE 600000
#define HID 128
#define NG 128
#define NC 10
#define NL 4
#define NW 9          // 1 emb + 2*NL layer weights

// ---------------- scratch ----------------
__device__ __align__(16) float g_h[NN * HID];
__device__ __align__(16) float g_agg[NN * HID];
__device__ __align__(16) float g_y1[NN * HID];
__device__ __align__(16) float g_y2[NN * HID];
__device__ float g_colsum[HID];
__device__ float g_colsq[HID];
__device__ __align__(16) float g_sc1[HID], g_sh1[HID], g_sc2[HID], g_sh2[HID];
__device__ __align__(16) float g_pooled[(NL + 1) * NG * HID];
__device__ float g_counts[NG];
// CSR
__device__ int g_cnt[NN];
__device__ int g_rowptr[NN + 1];
__device__ int g_cursor[NN];
__device__ int g_csr[NE];
// pre-split weights, transposed [n][k], bf16 hi/lo
__device__ __align__(16) __nv_bfloat16 g_whi[NW * HID * HID];
__device__ __align__(16) __nv_bfloat16 g_wlo[NW * HID * HID];

// ---------------- helpers ----------------
__device__ __forceinline__ uint32_t smem_u32(const void* p) {
    uint32_t a;
    asm("{ .reg .u64 t; cvta.to.shared.u64 t, %1; cvt.u32.u64 %0, t; }" : "=r"(a) : "l"(p));
    return a;
}
__device__ __forceinline__ void ldsm4(uint32_t* r, uint32_t addr) {
    asm volatile("ldmatrix.sync.aligned.m8n8.x4.shared.b16 {%0,%1,%2,%3}, [%4];"
                 : "=r"(r[0]), "=r"(r[1]), "=r"(r[2]), "=r"(r[3]) : "r"(addr));
}
__device__ __forceinline__ void ldsm2(uint32_t* r, uint32_t addr) {
    asm volatile("ldmatrix.sync.aligned.m8n8.x2.shared.b16 {%0,%1}, [%2];"
                 : "=r"(r[0]), "=r"(r[1]) : "r"(addr));
}
__device__ __forceinline__ void mma16816(float* c, const uint32_t* a, const uint32_t* b) {
    asm volatile(
        "mma.sync.aligned.m16n8k16.row.col.f32.bf16.bf16.f32 "
        "{%0,%1,%2,%3}, {%4,%5,%6,%7}, {%8,%9}, {%0,%1,%2,%3};"
        : "+f"(c[0]), "+f"(c[1]), "+f"(c[2]), "+f"(c[3])
        : "r"(a[0]), "r"(a[1]), "r"(a[2]), "r"(a[3]), "r"(b[0]), "r"(b[1]));
}

// tile leading dim: 128+8 -> 272B rows, conflict-free LDSM
#define LDT 136
#define TILE_BYTES (128 * LDT * 2)
#define SM_TOT (4 * TILE_BYTES)

// ---------------- weight pre-split: out[n][k] = bf16split(W[k][n]) ----------------
__global__ void wconv_k(const float* __restrict__ W, int m)
{
    const int o = blockIdx.x * 1024 + threadIdx.x;
    if (o >= HID * HID) return;
    const int n = o >> 7, k = o & 127;
    const float w = __ldg(&W[k * 128 + n]);
    const __nv_bfloat16 h = __float2bfloat16(w);
    g_whi[m * HID * HID + o] = h;
    g_wlo[m * HID * HID + o] = __float2bfloat16(w - __bfloat162float(h));
}

// ---------------- tensor GEMM: out[n,128] = f(A)[n,128] @ W[128,128] + bias ----------------
// MODE 0: a = A ; MODE 2: a = relu(A*bnsc + bnsh)
template <int MODE, bool STATS>
__global__ void __launch_bounds__(256) tgemm_k(
    const float* __restrict__ A,
    const float* __restrict__ bnsc, const float* __restrict__ bnsh,
    int widx, const float* __restrict__ bias,
    float* __restrict__ out, int n)
{
    extern __shared__ char smem[];
    __nv_bfloat16* Ahi = (__nv_bfloat16*)(smem);
    __nv_bfloat16* Alo = (__nv_bfloat16*)(smem + TILE_BYTES);
    __nv_bfloat16* Bhi = (__nv_bfloat16*)(smem + 2 * TILE_BYTES);
    __nv_bfloat16* Blo = (__nv_bfloat16*)(smem + 3 * TILE_BYTES);
    __shared__ float s_sum[128], s_sq[128];

    const int tid = threadIdx.x;
    const int lane = tid & 31;
    const int wid = tid >> 5;
    const int wm = wid & 3;
    const int wn = wid >> 2;
    const int row0 = blockIdx.x * 128;

    if (STATS && tid < 128) { s_sum[tid] = 0.f; s_sq[tid] = 0.f; }

    // ---- A tile: thread owns row tid/2, 64-col half; packed 16B smem stores ----
    {
        const int r = tid >> 1;
        const int row = row0 + r;
        const int cb = (tid & 1) * 64;
        const float4* Ar = (const float4*)(A + (size_t)row * 128 + cb);
#pragma unroll 2
        for (int i = 0; i < 8; i++) {          // 8 elems per iter (2 float4)
            float v[8] = {0, 0, 0, 0, 0, 0, 0, 0};
            if (row < n) {
                float4 a0 = Ar[2 * i], a1 = Ar[2 * i + 1];
                v[0] = a0.x; v[1] = a0.y; v[2] = a0.z; v[3] = a0.w;
                v[4] = a1.x; v[5] = a1.y; v[6] = a1.z; v[7] = a1.w;
                if (MODE == 2) {
                    const float* sc = bnsc + cb + i * 8;
                    const float* sh = bnsh + cb + i * 8;
#pragma unroll
                    for (int u = 0; u < 8; u++)
                        v[u] = fmaxf(fmaf(v[u], sc[u], sh[u]), 0.f);
                }
            }
            __nv_bfloat16 hi[8], lo[8];
#pragma unroll
            for (int u = 0; u < 8; u++) {
                hi[u] = __float2bfloat16(v[u]);
                lo[u] = __float2bfloat16(v[u] - __bfloat162float(hi[u]));
            }
            const int base = r * LDT + cb + i * 8;   // byte off = 272r+2cb+16i, 16B aligned
            *(float4*)&Ahi[base] = *(const float4*)hi;
            *(float4*)&Alo[base] = *(const float4*)lo;
        }
    }
    // ---- B tile: pure copy from pre-split transposed weights ----
    {
        const int r = tid >> 1;
        const int kc = (tid & 1) * 64;
        const float4* sh4 = (const float4*)(g_whi + (size_t)widx * HID * HID + r * 128 + kc);
        const float4* sl4 = (const float4*)(g_wlo + (size_t)widx * HID * HID + r * 128 + kc);
#pragma unroll
        for (int i = 0; i < 8; i++) {
            const int base = r * LDT + kc + i * 8;
            *(float4*)&Bhi[base] = sh4[i];
            *(float4*)&Blo[base] = sl4[i];
        }
    }
    __syncthreads();

    // ---- warp mma mainloop: 32x64 per warp ----
    float acc[2][8][4];
#pragma unroll
    for (int mt = 0; mt < 2; mt++)
#pragma unroll
        for (int j = 0; j < 8; j++)
#pragma unroll
            for (int u = 0; u < 4; u++) acc[mt][j][u] = 0.f;

    const uint32_t sAhi = smem_u32(Ahi), sAlo = smem_u32(Alo);
    const uint32_t sBhi = smem_u32(Bhi), sBlo = smem_u32(Blo);

    const int aRow = wm * 32 + (lane & 15);
    const int aCol = (lane >> 4) * 8;
    const int bRow = wn * 64 + (lane & 7);
    const int bCol = ((lane >> 3) & 1) * 8;

#pragma unroll
    for (int ks = 0; ks < 8; ks++) {
        uint32_t ahi[2][4], alo[2][4], bhi[8][2], blo[8][2];
        const int kc = ks * 16;
#pragma unroll
        for (int mt = 0; mt < 2; mt++) {
            const uint32_t off = ((aRow + mt * 16) * LDT + kc + aCol) * 2;
            ldsm4(ahi[mt], sAhi + off);
            ldsm4(alo[mt], sAlo + off);
        }
#pragma unroll
        for (int j = 0; j < 8; j++) {
            const uint32_t off = ((bRow + j * 8) * LDT + kc + bCol) * 2;
            ldsm2(bhi[j], sBhi + off);
            ldsm2(blo[j], sBlo + off);
        }
#pragma unroll
        for (int mt = 0; mt < 2; mt++)
#pragma unroll
            for (int j = 0; j < 8; j++) {
                mma16816(acc[mt][j], ahi[mt], bhi[j]);
                mma16816(acc[mt][j], ahi[mt], blo[j]);
                mma16816(acc[mt][j], alo[mt], bhi[j]);
            }
    }

    // ---- epilogue: bias + store (+ fused column stats) ----
    float st[8][4];
    if (STATS) {
#pragma unroll
        for (int j = 0; j < 8; j++)
#pragma unroll
            for (int u = 0; u < 4; u++) st[j][u] = 0.f;
    }
#pragma unroll
    for (int mt = 0; mt < 2; mt++) {
        const int r_lo = row0 + wm * 32 + mt * 16 + (lane >> 2);
        const int r_hi = r_lo + 8;
#pragma unroll
        for (int j = 0; j < 8; j++) {
            const int c = wn * 64 + j * 8 + (lane & 3) * 2;
            const float b0 = bias[c], b1 = bias[c + 1];
            if (r_lo < n) {
                const float v0 = acc[mt][j][0] + b0, v1 = acc[mt][j][1] + b1;
                *(float2*)(out + (size_t)r_lo * 128 + c) = make_float2(v0, v1);
                if (STATS) {
                    st[j][0] += v0; st[j][1] += v1;
                    st[j][2] = fmaf(v0, v0, st[j][2]); st[j][3] = fmaf(v1, v1, st[j][3]);
                }
            }
            if (r_hi < n) {
                const float v0 = acc[mt][j][2] + b0, v1 = acc[mt][j][3] + b1;
                *(float2*)(out + (size_t)r_hi * 128 + c) = make_float2(v0, v1);
                if (STATS) {
                    st[j][0] += v0; st[j][1] += v1;
                    st[j][2] = fmaf(v0, v0, st[j][2]); st[j][3] = fmaf(v1, v1, st[j][3]);
                }
            }
        }
    }
    if (STATS) {
#pragma unroll
        for (int j = 0; j < 8; j++)
#pragma unroll
            for (int u = 0; u < 4; u++) {
                st[j][u] += __shfl_xor_sync(0xFFFFFFFF, st[j][u], 4);
                st[j][u] += __shfl_xor_sync(0xFFFFFFFF, st[j][u], 8);
                st[j][u] += __shfl_xor_sync(0xFFFFFFFF, st[j][u], 16);
            }
        if (lane < 4) {
#pragma unroll
            for (int j = 0; j < 8; j++) {
                const int c = wn * 64 + j * 8 + lane * 2;
                atomicAdd(&s_sum[c], st[j][0]);
                atomicAdd(&s_sum[c + 1], st[j][1]);
                atomicAdd(&s_sq[c], st[j][2]);
                atomicAdd(&s_sq[c + 1], st[j][3]);
            }
        }
        __syncthreads();
        if (tid < 128) {
            atomicAdd(&g_colsum[tid], s_sum[tid]);
            atomicAdd(&g_colsq[tid], s_sq[tid]);
        }
    }
}

// ---------------- finalize BN ----------------
__global__ void bnfin_k(const float* __restrict__ gam, const float* __restrict__ bet,
                        float* __restrict__ sc, float* __restrict__ sh)
{
    const int c = threadIdx.x;
    const float inv_n = 1.0f / (float)NN;
    const float m = g_colsum[c] * inv_n;
    const float var = g_colsq[c] * inv_n - m * m;
    const float s = gam[c] * rsqrtf(var + 1e-5f);
    sc[c] = s;
    sh[c] = bet[c] - m * s;
    g_colsum[c] = 0.0f;
    g_colsq[c] = 0.0f;
}

// ---------------- CSR build ----------------
__global__ void hist_k(const int* __restrict__ dst)
{
    const int e = blockIdx.x * 256 + threadIdx.x;
    if (e < NE) atomicAdd(&g_cnt[dst[e]], 1);
}

__global__ void __launch_bounds__(1024) scan_k()
{
    __shared__ int sm[1024];
    const int t = threadIdx.x;
    const int per = (NN + 1023) / 1024;
    const int beg = t * per;
    const int end = min(beg + per, NN);
    int s = 0;
    for (int i = beg; i < end; i++) s += g_cnt[i];
    sm[t] = s;
    __syncthreads();
    for (int off = 1; off < 1024; off <<= 1) {
        int v = (t >= off) ? sm[t - off] : 0;
        __syncthreads();
        sm[t] += v;
        __syncthreads();
    }
    int run = sm[t] - s;   // exclusive prefix
    for (int i = beg; i < end; i++) {
        const int c = g_cnt[i];
        g_rowptr[i] = run;
        g_cursor[i] = run;
        run += c;
    }
    if (t == 1023) g_rowptr[NN] = sm[1023];
}

__global__ void fill_k(const int* __restrict__ src, const int* __restrict__ dst)
{
    const int e = blockIdx.x * 256 + threadIdx.x;
    if (e >= NE) return;
    const int pos = atomicAdd(&g_cursor[dst[e]], 1);
    g_csr[pos] = src[e];
}

// ---------------- gather: agg[v] = (1+eps)*h[v] + sum_{u->v} h[u] ----------------
__global__ void __launch_bounds__(256) gather_k(const float* __restrict__ epsPtr, int layer)
{
    const int node = blockIdx.x * 8 + (threadIdx.x >> 5);
    if (node >= NN) return;
    const int lane = threadIdx.x & 31;
    const float oe = 1.0f + epsPtr[layer];
    const float4 hv = *(const float4*)(&g_h[(size_t)node * 128 + lane * 4]);
    float4 acc = make_float4(oe * hv.x, oe * hv.y, oe * hv.z, oe * hv.w);
    const int rp0 = g_rowptr[node], rp1 = g_rowptr[node + 1];
    for (int e = rp0; e < rp1; e++) {
        const int s = g_csr[e];
        const float4 v = *(const float4*)(&g_h[(size_t)s * 128 + lane * 4]);
        acc.x += v.x; acc.y += v.y; acc.z += v.z; acc.w += v.w;
    }
    *(float4*)(&g_agg[(size_t)node * 128 + lane * 4]) = acc;
}

// ---------------- residual update + pooling ----------------
template <bool UPDATE>
__global__ void __launch_bounds__(256) pool_k(const float* __restrict__ y2,
                                              const float* __restrict__ sc,
                                              const float* __restrict__ sh,
                                              const int* __restrict__ batch,
                                              float* __restrict__ pooled)
{
    const int node = blockIdx.x * 8 + (threadIdx.x >> 5);
    if (node >= NN) return;
    const int lane = threadIdx.x & 31;
    const int g = batch[node];
    float4 hv = *reinterpret_cast<const float4*>(&g_h[node * 128 + lane * 4]);
    if (UPDATE) {
        const float4 yv = *reinterpret_cast<const float4*>(&y2[node * 128 + lane * 4]);
        const float4 scv = *reinterpret_cast<const float4*>(&sc[lane * 4]);
        const float4 shv = *reinterpret_cast<const float4*>(&sh[lane * 4]);
        hv.x += fmaxf(fmaf(yv.x, scv.x, shv.x), 0.0f);
        hv.y += fmaxf(fmaf(yv.y, scv.y, shv.y), 0.0f);
        hv.z += fmaxf(fmaf(yv.z, scv.z, shv.z), 0.0f);
        hv.w += fmaxf(fmaf(yv.w, scv.w, shv.w), 0.0f);
        *reinterpret_cast<float4*>(&g_h[node * 128 + lane * 4]) = hv;
    }
    atomicAdd(reinterpret_cast<float4*>(&pooled[g * 128 + lane * 4]), hv);
}

// ---------------- counts ----------------
__global__ void counts_k(const int* __restrict__ batch)
{
    const int i = blockIdx.x * 256 + threadIdx.x;
    if (i < NN) atomicAdd(&g_counts[batch[i]], 1.0f);
}

// ---------------- heads ----------------
__global__ void head_k(const float* __restrict__ pw, const float* __restrict__ pb,
                       float* __restrict__ out)
{
    const int g = blockIdx.x;
    const int c = threadIdx.x;
    if (c >= NC) return;
    const float inv_cnt = 1.0f / fmaxf(g_counts[g], 1.0f);
    float acc = 0.0f;
#pragma unroll
    for (int l = 0; l <= NL; l++) {
        const float* p = &g_pooled[(l * NG + g) * HID];
        float a = 0.0f;
#pragma unroll 8
        for (int f = 0; f < HID; f++)
            a = fmaf(p[f], pw[(l * HID + f) * NC + c], a);
        acc += a * inv_cnt + pb[l * NC + c];
    }
    out[g * NC + c] = acc;
}

// ---------------- launch ----------------
extern "C" void kernel_launch(void* const* d_in, const int* in_sizes, int n_in,
                              void* d_out, int out_size)
{
    const float* x     = (const float*)d_in[0];
    const int*   ei    = (const int*)d_in[1];
    const int*   batch = (const int*)d_in[2];
    const float* emb_w = (const float*)d_in[3];
    const float* emb_b = (const float*)d_in[4];
    const float* eps   = (const float*)d_in[5];
    const float* w1    = (const float*)d_in[6];
    const float* b1    = (const float*)d_in[7];
    const float* bn1g  = (const float*)d_in[8];
    const float* bn1b  = (const float*)d_in[9];
    const float* w2    = (const float*)d_in[10];
    const float* b2    = (const float*)d_in[11];
    const float* bng   = (const float*)d_in[12];
    const float* bnb   = (const float*)d_in[13];
    const float* pw    = (const float*)d_in[14];
    const float* pb    = (const float*)d_in[15];
    float*       out   = (float*)d_out;

    void *p_h, *p_agg, *p_y1, *p_y2, *p_pooled, *p_counts, *p_colsum, *p_colsq;
    void *p_sc1, *p_sh1, *p_sc2, *p_sh2, *p_cnt;
    cudaGetSymbolAddress(&p_h,      g_h);
    cudaGetSymbolAddress(&p_agg,    g_agg);
    cudaGetSymbolAddress(&p_y1,     g_y1);
    cudaGetSymbolAddress(&p_y2,     g_y2);
    cudaGetSymbolAddress(&p_pooled, g_pooled);
    cudaGetSymbolAddress(&p_counts, g_counts);
    cudaGetSymbolAddress(&p_colsum, g_colsum);
    cudaGetSymbolAddress(&p_colsq,  g_colsq);
    cudaGetSymbolAddress(&p_sc1,    g_sc1);
    cudaGetSymbolAddress(&p_sh1,    g_sh1);
    cudaGetSymbolAddress(&p_sc2,    g_sc2);
    cudaGetSymbolAddress(&p_sh2,    g_sh2);
    cudaGetSymbolAddress(&p_cnt,    g_cnt);

    cudaFuncSetAttribute(tgemm_k<0, false>, cudaFuncAttributeMaxDynamicSharedMemorySize, SM_TOT);
    cudaFuncSetAttribute(tgemm_k<0, true>,  cudaFuncAttributeMaxDynamicSharedMemorySize, SM_TOT);
    cudaFuncSetAttribute(tgemm_k<2, true>,  cudaFuncAttributeMaxDynamicSharedMemorySize, SM_TOT);

    cudaMemsetAsync(p_pooled, 0, sizeof(float) * (NL + 1) * NG * HID);
    cudaMemsetAsync(p_counts, 0, sizeof(float) * NG);
    cudaMemsetAsync(p_colsum, 0, sizeof(float) * HID);
    cudaMemsetAsync(p_colsq,  0, sizeof(float) * HID);
    cudaMemsetAsync(p_cnt,    0, sizeof(int) * NN);

    // pre-split weights: m=0 emb, m=1+2l w1[l], m=2+2l w2[l]
    wconv_k<<<16, 1024>>>(emb_w, 0);
    for (int l = 0; l < NL; l++) {
        wconv_k<<<16, 1024>>>(w1 + (size_t)l * HID * HID, 1 + 2 * l);
        wconv_k<<<16, 1024>>>(w2 + (size_t)l * HID * HID, 2 + 2 * l);
    }

    // CSR build (by dst, storing src)
    hist_k<<<(NE + 255) / 256, 256>>>(ei + NE);
    scan_k<<<1, 1024>>>();
    fill_k<<<(NE + 255) / 256, 256>>>(ei, ei + NE);

    counts_k<<<(NN + 255) / 256, 256>>>(batch);

    const int GB = (NN + 127) / 128;

    // embedding
    tgemm_k<0, false><<<GB, 256, SM_TOT>>>(x, nullptr, nullptr, 0, emb_b, (float*)p_h, NN);
    pool_k<false><<<(NN + 7) / 8, 256>>>(nullptr, nullptr, nullptr, batch, (float*)p_pooled);

    for (int l = 0; l < NL; l++) {
        gather_k<<<(NN + 7) / 8, 256>>>(eps, l);

        tgemm_k<0, true><<<GB, 256, SM_TOT>>>((const float*)p_agg, nullptr, nullptr,
                                              1 + 2 * l, b1 + l * HID, (float*)p_y1, NN);
        bnfin_k<<<1, 128>>>(bn1g + l * HID, bn1b + l * HID, (float*)p_sc1, (float*)p_sh1);

        tgemm_k<2, true><<<GB, 256, SM_TOT>>>((const float*)p_y1, (const float*)p_sc1,
                                              (const float*)p_sh1,
                                              2 + 2 * l, b2 + l * HID, (float*)p_y2, NN);
        bnfin_k<<<1, 128>>>(bng + l * HID, bnb + l * HID, (float*)p_sc2, (float*)p_sh2);

        pool_k<true><<<(NN + 7) / 8, 256>>>((const float*)p_y2, (const float*)p_sc2,
                                            (const float*)p_sh2, batch,
                                            (float*)p_pooled + (size_t)(l + 1) * NG * HID);
    }

    head_k<<<NG, 32>>>(pw, pb, out);
}